// round 17
// baseline (speedup 1.0000x reference)
#include <cuda_runtime.h>
#include <cuda_bf16.h>

// Problem constants (fixed shapes)
#define S_NUM   16
#define T_MAX   11
#define ROWS    64
#define HID     768
#define SEQ     512

#define BERT_ELEMS   (S_NUM * SEQ * HID)        // 6291456
#define MTL_OFF      BERT_ELEMS
#define MTL_ELEMS    (S_NUM * HID)              // 12288
#define PROBS_OFF    (MTL_OFF + MTL_ELEMS)

#define H4           (HID / 4)                  // 192
#define E4_PER_SLICE (SEQ * H4)                 // 98304 float4 per slice
#define MTL4_PER_S   (HID / 4)                  // 192

#define BLK_PER_S    384                        // bert blocks per slice
#define N_WAITERS    (S_NUM * BLK_PER_S)        // 6144
#define GRID_TOTAL   (S_NUM + N_WAITERS)        // 6160

// Scratch (no device mallocs allowed; statics zero-initialized)
__device__ float    g_w[ROWS];
__device__ unsigned g_flag;                     // 1 = all weights published
__device__ unsigned g_pcnt;                     // finished producers
__device__ unsigned g_dcnt;                     // finished waiters

// ---------------------------------------------------------------------------
// Single fused kernel. 1-D grid, 256 threads/block.
//  bid < 16          : producer for slice bid — dots, softmax, publish g_w,
//                      16th producer sets g_flag; then mtl + probs.
//                      Producers are the FIRST 16 bids -> wave-1 resident.
//  bid >= 16         : bert streaming block. Issues its 4 streaming loads,
//                      then waits on g_flag (first poll free for waves>=2),
//                      FMAs, stores. Last waiter resets flag/counters.
// ---------------------------------------------------------------------------
__global__ void __launch_bounds__(256)
fused_kernel(const float4* __restrict__ bert,   // [64, E4_PER_SLICE]
             const float4* __restrict__ hist4,  // [64, H4]
             const float4* __restrict__ mtl4,   // [64, H4]
             const float4* __restrict__ W4,     // [H4]
             const float*  __restrict__ b,      // [1]
             const int*    __restrict__ smask,  // [64]
             float*        __restrict__ out)
{
    const int tid = threadIdx.x;
    const int bid = blockIdx.x;

    if (bid < S_NUM) {
        // ------------------- producer for slice s = bid -------------------
        const int s = bid;
        int off = 0;
        for (int i = 0; i < s; i++) off += __ldg(smask + i);
        const int n = __ldg(smask + s);

        __shared__ float s_d[T_MAX];
        __shared__ float s_w[T_MAX];

        const int lane = tid & 31;
        const int wid  = tid >> 5;              // 0..7
        const float bias = __ldg(b);

        for (int j = wid; j < n; j += 8) {
            const float4* h = hist4 + (size_t)(off + j) * H4;
            float acc = 0.f;
            #pragma unroll
            for (int k = lane; k < H4; k += 32) {
                float4 w = __ldg(W4 + k);
                float4 a = __ldg(h + k);
                acc += a.x*w.x + a.y*w.y + a.z*w.z + a.w*w.w;
            }
            #pragma unroll
            for (int d = 16; d > 0; d >>= 1)
                acc += __shfl_xor_sync(0xffffffffu, acc, d);
            if (lane == 0) s_d[j] = acc + bias;
        }
        __syncthreads();

        if (tid == 0) {
            float e[T_MAX];
            float denom = 0.f;
            for (int j = 0; j < n; j++) {
                float v = expf(s_d[j]);
                e[j] = v;
                denom += v;
            }
            float inv = 1.f / denom;
            for (int j = 0; j < n; j++) {
                float wv = e[j] * inv;
                s_w[j] = wv;
                g_w[off + j] = wv;
            }
            __threadfence();                    // publish g_w before counting
            unsigned old = atomicAdd(&g_pcnt, 1u);
            if (old == S_NUM - 1)
                atomicExch(&g_flag, 1u);        // release: all 16 published
        }
        __syncthreads();

        // mtl segment-sum for this slice (weights already in s_w)
        if (tid < MTL4_PER_S) {
            float4 acc = make_float4(0.f, 0.f, 0.f, 0.f);
            for (int j = 0; j < n; j++) {
                float w  = s_w[j];
                float4 v = __ldg(mtl4 + (off + j) * H4 + tid);
                acc.x += w*v.x; acc.y += w*v.y; acc.z += w*v.z; acc.w += w*v.w;
            }
            ((float4*)(out + MTL_OFF))[s * MTL4_PER_S + tid] = acc;
        }
        // probs row
        if (tid < T_MAX) {
            int pad = T_MAX - n;
            out[PROBS_OFF + s * T_MAX + tid] = (tid >= pad) ? s_w[tid - pad] : 0.f;
        }
        return;
    }

    // --------------------------- bert waiter ---------------------------
    const int idx = bid - S_NUM;                // 0..6143
    const int s   = idx / BLK_PER_S;
    const int bx  = idx - s * BLK_PER_S;
    const int e   = bx * 256 + tid;

    int off = 0;
    for (int i = 0; i < s; i++) off += __ldg(smask + i);
    const int n = __ldg(smask + s);

    float4* out4 = (float4*)out + (size_t)s * E4_PER_SLICE;

    if (n == 4) {
        // issue all 4 streaming loads before the wait
        float4 a0 = __ldcs(bert + (size_t)(off + 0) * E4_PER_SLICE + e);
        float4 a1 = __ldcs(bert + (size_t)(off + 1) * E4_PER_SLICE + e);
        float4 a2 = __ldcs(bert + (size_t)(off + 2) * E4_PER_SLICE + e);
        float4 a3 = __ldcs(bert + (size_t)(off + 3) * E4_PER_SLICE + e);

        if (tid == 0) {
            while (__ldcg(&g_flag) == 0u) __nanosleep(200);
            __threadfence();                    // acquire: order g_w reads
        }
        __syncthreads();

        float w0 = g_w[off + 0];
        float w1 = g_w[off + 1];
        float w2 = g_w[off + 2];
        float w3 = g_w[off + 3];

        float4 acc;
        acc.x = w0*a0.x + w1*a1.x + w2*a2.x + w3*a3.x;
        acc.y = w0*a0.y + w1*a1.y + w2*a2.y + w3*a3.y;
        acc.z = w0*a0.z + w1*a1.z + w2*a2.z + w3*a3.z;
        acc.w = w0*a0.w + w1*a1.w + w2*a2.w + w3*a3.w;
        __stcs(out4 + e, acc);
    } else {
        // generic path (any n 1..T_MAX)
        if (tid == 0) {
            while (__ldcg(&g_flag) == 0u) __nanosleep(200);
            __threadfence();
        }
        __syncthreads();

        float4 acc = make_float4(0.f, 0.f, 0.f, 0.f);
        for (int j = 0; j < n; j++) {
            float w  = g_w[off + j];
            float4 v = __ldcs(bert + (size_t)(off + j) * E4_PER_SLICE + e);
            acc.x += w*v.x; acc.y += w*v.y; acc.z += w*v.z; acc.w += w*v.w;
        }
        __stcs(out4 + e, acc);
    }

    // ---- reset protocol: last waiter clears flag/counters for next replay.
    // The increment is AFTER this block's poll passed, so when old==N-1 every
    // waiter has already observed flag==1; clearing it cannot strand anyone.
    if (tid == 0) {
        __threadfence();
        unsigned old = atomicAdd(&g_dcnt, 1u);
        if (old == N_WAITERS - 1) {
            g_flag = 0u;
            g_pcnt = 0u;
            g_dcnt = 0u;
            __threadfence();
        }
    }
}

extern "C" void kernel_launch(void* const* d_in, const int* in_sizes, int n_in,
                              void* d_out, int out_size)
{
    const float* bert  = (const float*)d_in[0];   // [64, 512, 768]
    const float* hist  = (const float*)d_in[1];   // [64, 768]
    const float* mtl   = (const float*)d_in[2];   // [64, 768]
    const float* W     = (const float*)d_in[3];   // [1, 768]
    const float* b     = (const float*)d_in[4];   // [1]
    const int*   smask = (const int*)d_in[5];     // [64]
    float* out = (float*)d_out;

    fused_kernel<<<GRID_TOTAL, 256>>>((const float4*)bert, (const float4*)hist,
                                      (const float4*)mtl, (const float4*)W,
                                      b, smask, out);
}